// round 2
// baseline (speedup 1.0000x reference)
#include <cuda_runtime.h>
#include <cstdint>

// Problem constants
#define B_    8
#define N_    256
#define T_    50
#define FEAT  1799
#define TOK   128
#define BN    2048        // B_*N_
#define KMAX  8           // kept EMA terms; dropped relative mass <= ~1e-8
#define G     16          // (b,n) rows per block
#define FPAD  1800        // padded feature stride in smem (7200 B rows, 16B-aligned)

#define SMEM_BYTES (G*FPAD*4 + G*KMAX*4 + G*4 + G*KMAX*4)

extern __shared__ float s_dyn[];

// ---------------------------------------------------------------------------
// Single fused kernel. One block handles G=16 (b,n) rows.
//
// Phase 0: 16 threads scan the 50 mask entries of their row. Processing order
//   in the reference is t = T-1..0, so the final EMA is
//     ema = sum over masked t (ASCENDING) of 0.9 * 0.1^rank * token(t)
//   truncated at KMAX=8 terms (0.1^8 relative tail).
//   Mask dtype is sniffed from bit patterns (float32 words 0x3F800000,
//   int32 words 0/1, packed uint8 words exceed 1 quickly).
//
// Phase 1: fbar[g][f] = sum_k w_k * feats[bn,t_k,f]   (coalesced, HBM-bound)
//
// Phase 2: out[g][d] = dot(fbar[g], W[d]) + sumw[g]*b[d]
//   256 threads = (d 0..127) x (two 8-row halves); packed fma.rn.f32x2,
//   W rows streamed through L1/L2, fbar read via broadcast LDS.128.
// ---------------------------------------------------------------------------
__global__ __launch_bounds__(256, 1)
void ema_linear_kernel(const float* __restrict__ feats,
                       const void*  __restrict__ masks,
                       const float* __restrict__ Wm,
                       const float* __restrict__ bias,
                       float* __restrict__ out) {
    float* fbar = s_dyn;                      // G * FPAD
    float* sw   = s_dyn + G * FPAD;           // G * KMAX   weights
    float* ssum = sw + G * KMAX;              // G          sum of weights
    int*   st   = (int*)(ssum + G);           // G * KMAX   row offsets (pre-scaled)

    __shared__ int smode;

    const int tid = threadIdx.x;
    const int bn0 = blockIdx.x * G;

    // ---- Phase 0a: sniff mask dtype (thread 0) ----
    if (tid == 0) {
        const unsigned int* wds = (const unsigned int*)masks;
        int mode = 0;  // 0=int32, 1=uint8, 2=float32
        for (int i = 0; i < 1024; ++i) {
            unsigned int v = wds[i];
            if (v == 0x3F800000u) { mode = 2; break; }
            if (v > 1u)           { mode = 1; break; }
        }
        smode = mode;
    }
    __syncthreads();

    // ---- Phase 0b: per-row mask scan -> (t_k, w_k) ----
    if (tid < G) {
        const int mode = smode;
        const int bn   = bn0 + tid;
        const int base = bn * T_;
        const float*         mf = (const float*)masks;
        const int*           mi = (const int*)masks;
        const unsigned char* mb = (const unsigned char*)masks;

        int   tarr[KMAX];
        float warr[KMAX];
        int   cnt = 0;
        float w   = 0.9f;
        float sum = 0.f;
        for (int t = 0; t < T_ && cnt < KMAX; ++t) {
            bool m;
            if (mode == 2)      m = (mf[base + t] != 0.f);
            else if (mode == 1) m = (mb[base + t] != 0);
            else                m = (mi[base + t] != 0);
            if (m) { tarr[cnt] = t; warr[cnt] = w; sum += w; w *= 0.1f; ++cnt; }
        }
        int tpad = (cnt > 0) ? tarr[cnt - 1] : 0;   // zero-weight dup (L1-hit cheap)
        for (int k = cnt; k < KMAX; ++k) { tarr[k] = tpad; warr[k] = 0.f; }

#pragma unroll
        for (int k = 0; k < KMAX; ++k) {
            sw[tid * KMAX + k] = warr[k];
            st[tid * KMAX + k] = tarr[k] * FEAT;
        }
        ssum[tid] = sum;
    }
    __syncthreads();

    // ---- Phase 1: weighted reduction over selected time rows ----
    for (int g = 0; g < G; ++g) {
        const float* base = feats + (size_t)(bn0 + g) * (T_ * FEAT);
        float wk[KMAX]; int ok[KMAX];
#pragma unroll
        for (int k = 0; k < KMAX; ++k) { wk[k] = sw[g * KMAX + k]; ok[k] = st[g * KMAX + k]; }
#pragma unroll
        for (int fi = 0; fi < 8; ++fi) {
            int f = tid + fi * 256;
            float acc = 0.f;
            if (f < FEAT) {
#pragma unroll
                for (int k = 0; k < KMAX; ++k)
                    acc += wk[k] * __ldg(base + ok[k] + f);
            }
            if (f < FPAD) fbar[g * FPAD + f] = acc;   // f==1799 pad -> 0
        }
    }
    __syncthreads();

    // ---- Phase 2: GEMM ----
    const int d  = tid & (TOK - 1);
    const int gb = (tid >> 7) * (G / 2);
    const float* wr = Wm + (size_t)d * FEAT;

    unsigned long long acc[G / 2];
#pragma unroll
    for (int g = 0; g < G / 2; ++g) acc[g] = 0ull;

    for (int f = 0; f < 1792; f += 4) {
        float w0 = wr[f], w1 = wr[f + 1], w2 = wr[f + 2], w3 = wr[f + 3];
        unsigned long long wp0, wp1;
        asm("mov.b64 %0, {%1, %2};" : "=l"(wp0) : "f"(w0), "f"(w1));
        asm("mov.b64 %0, {%1, %2};" : "=l"(wp1) : "f"(w2), "f"(w3));
#pragma unroll
        for (int g = 0; g < G / 2; ++g) {
            ulonglong2 fv = *(const ulonglong2*)(fbar + (gb + g) * FPAD + f);
            asm("fma.rn.f32x2 %0, %1, %2, %0;" : "+l"(acc[g]) : "l"(wp0), "l"(fv.x));
            asm("fma.rn.f32x2 %0, %1, %2, %0;" : "+l"(acc[g]) : "l"(wp1), "l"(fv.y));
        }
    }

    float res[G / 2];
#pragma unroll
    for (int g = 0; g < G / 2; ++g) {
        float lo, hi;
        asm("mov.b64 {%0, %1}, %2;" : "=f"(lo), "=f"(hi) : "l"(acc[g]));
        res[g] = lo + hi;
    }
    // Scalar tail f = 1792..1798
    for (int f = 1792; f < FEAT; ++f) {
        float wv = wr[f];
#pragma unroll
        for (int g = 0; g < G / 2; ++g) res[g] += wv * fbar[(gb + g) * FPAD + f];
    }

    const float bd = bias[d];
#pragma unroll
    for (int g = 0; g < G / 2; ++g) {
        out[(size_t)(bn0 + gb + g) * TOK + d] = res[g] + ssum[gb + g] * bd;
    }
}

// ---------------------------------------------------------------------------
extern "C" void kernel_launch(void* const* d_in, const int* in_sizes, int n_in,
                              void* d_out, int out_size) {
    const float* feats = (const float*)d_in[0];
    const void*  masks = d_in[1];
    const float* Wm    = (const float*)d_in[2];
    const float* bias  = (const float*)d_in[3];
    float*       out   = (float*)d_out;

    cudaFuncSetAttribute(ema_linear_kernel,
                         cudaFuncAttributeMaxDynamicSharedMemorySize, SMEM_BYTES);

    ema_linear_kernel<<<BN / G, 256, SMEM_BYTES>>>(feats, masks, Wm, bias, out);
}